// round 15
// baseline (speedup 1.0000x reference)
#include <cuda_runtime.h>
#include <math.h>

// inputs: x[f32] (unused), src[i32 E], dst[i32 E], path_len[i32 E], b[f32 5].
// output: f32 N*N.  out = zeros; out[src[i],dst[i]] = b[min(plen[i],5)-1],
// LAST duplicate (highest i) wins.
//
// Multisplit row-binning, no global atomics. NCTA=1024 keeps the latency-bound
// pair passes at ~87% occupancy (proven R14 win). This round: u16 counts
// (halved scan-chain traffic), separate 32-bit offset array, fused
// segsum+rowtot launch.
//   H2 : per-CTA smem histogram of src -> g_cnt16[cta][row]  (u16, 16 MB)
//   K1 : blocks 0..1023: segment sums (32 segs x 32) -> g_seg[seg][row]
//        blocks 1024..1055: per-row totals over all ctas -> g_total
//   K2 : 1-CTA exclusive scan of g_total -> g_rowStart
//   K2b: per-row running bases over segs -> g_segstart
//   K3 : per-(seg,row): 32 u16 counts -> absolute offsets -> g_off (int)
//   B2 : per-CTA smem cursors from g_off; slot = smem atomicAdd ->
//        g_bins[slot] = {key, dst}
//   AP : one CTA per row: smem atomicMax(tile[dst], key) (key monotone in
//        pair index i), dense coalesced row store (__stcs streaming).

#ifndef MAX_PATH_DISTANCE
#define MAX_PATH_DISTANCE 5
#endif

#define N_MAX 8192
#define E_MAX (4 * 1024 * 1024)
#define NCTA  1024
#define NSEG  32
#define SEGW  (NCTA / NSEG)          // 32

__device__ unsigned short g_cnt16[NCTA * N_MAX];  // [cta][row], 16 MB
__device__ int  g_off[NCTA * N_MAX];              // [cta][row], 32 MB
__device__ int  g_seg[NSEG * N_MAX];              // [seg][row], 1 MB
__device__ int  g_segstart[NSEG * N_MAX];
__device__ int  g_total[N_MAX];
__device__ int  g_rowStart[N_MAX];
__device__ int2 g_bins[E_MAX];                    // 32 MB

// ---------------- H2: per-CTA smem histogram ----------------
__global__ void __launch_bounds__(256) hist2_kernel(const int* __restrict__ src,
                                                    int n_pairs, int chunk) {
    __shared__ int cnt[N_MAX];
    int t = threadIdx.x, nt = blockDim.x, c = blockIdx.x;
    for (int i = t; i < N_MAX; i += nt) cnt[i] = 0;
    __syncthreads();

    int begin = c * chunk;                       // chunk is a multiple of 4
    int end = min(begin + chunk, n_pairs);
    if (begin < end) {
        int nfull = begin + ((end - begin) & ~3);
        for (int base = begin + t * 4; base < nfull; base += nt * 4) {
            int4 s = *reinterpret_cast<const int4*>(src + base);
            atomicAdd(&cnt[s.x], 1); atomicAdd(&cnt[s.y], 1);
            atomicAdd(&cnt[s.z], 1); atomicAdd(&cnt[s.w], 1);
        }
        for (int k = nfull + t; k < end; k += nt) atomicAdd(&cnt[src[k]], 1);
    }
    __syncthreads();

    // u16 writeout, 2 per thread word-packed (coalesced, counts < 65536)
    for (int i = t; i < N_MAX / 2; i += nt) {
        unsigned int packed = (unsigned)cnt[i * 2] |
                              ((unsigned)cnt[i * 2 + 1] << 16);
        reinterpret_cast<unsigned int*>(g_cnt16 + c * N_MAX)[i] = packed;
    }
}

// ---------------- K1 fused: segsum (blocks 0..1023) + rowtot ----------------
__global__ void __launch_bounds__(256) segsum_rowtot_kernel() {
    int blk = blockIdx.x;
    if (blk < (NSEG * N_MAX) / 256) {
        int t = blk * 256 + threadIdx.x;             // t = seg*N_MAX + row
        int seg = t >> 13;                // / N_MAX
        int row = t & (N_MAX - 1);
        int sum = 0;
#pragma unroll
        for (int j = 0; j < SEGW; ++j)
            sum += g_cnt16[(seg * SEGW + j) * N_MAX + row];  // coalesced lanes
        g_seg[seg * N_MAX + row] = sum;
    } else {
        int row = (blk - (NSEG * N_MAX) / 256) * 256 + threadIdx.x;
        if (row >= N_MAX) return;
        int sum = 0;
#pragma unroll 32
        for (int c = 0; c < NCTA; ++c)
            sum += g_cnt16[c * N_MAX + row];             // coalesced lanes
        g_total[row] = sum;
    }
}

// ---------------- K2: exclusive scan of totals ----------------
__global__ void __launch_bounds__(1024) scan_kernel(int n) {
    __shared__ int sdata[1024];
    int t = threadIdx.x;

    int vals[8];
    int sum = 0;
#pragma unroll
    for (int j = 0; j < 8; ++j) {
        int r = t * 8 + j;
        vals[j] = (r < n) ? g_total[r] : 0;
        sum += vals[j];
    }
    sdata[t] = sum;
    __syncthreads();
    for (int off = 1; off < 1024; off <<= 1) {
        int v = (t >= off) ? sdata[t - off] : 0;
        __syncthreads();
        sdata[t] += v;
        __syncthreads();
    }
    int run = sdata[t] - sum;                    // exclusive prefix over rows
#pragma unroll
    for (int j = 0; j < 8; ++j) {
        int r = t * 8 + j;
        if (r < n) g_rowStart[r] = run;
        run += vals[j];
    }
}

// ---------------- K2b: per-(seg,row) bases ----------------
__global__ void __launch_bounds__(256) segstart_kernel() {
    int row = blockIdx.x * blockDim.x + threadIdx.x;
    if (row >= N_MAX) return;
    int run = g_rowStart[row];
#pragma unroll
    for (int k = 0; k < NSEG; ++k) {
        g_segstart[k * N_MAX + row] = run;       // coalesced
        run += g_seg[k * N_MAX + row];
    }
}

// ---------------- K3: u16 counts -> absolute offsets in g_off ----------------
__global__ void __launch_bounds__(256) offsets_kernel() {
    int t = blockIdx.x * blockDim.x + threadIdx.x;   // t = seg*N_MAX + row
    if (t >= NSEG * N_MAX) return;
    int seg = t >> 13;
    int row = t & (N_MAX - 1);

    int v[SEGW];
#pragma unroll
    for (int j = 0; j < SEGW; ++j)                   // independent loads, MLP 32
        v[j] = g_cnt16[(seg * SEGW + j) * N_MAX + row];

    int run = g_segstart[seg * N_MAX + row];
#pragma unroll
    for (int j = 0; j < SEGW; ++j) {
        g_off[(seg * SEGW + j) * N_MAX + row] = run;
        run += v[j];
    }
}

// ---------------- B2: place pairs via smem cursors ----------------
__global__ void __launch_bounds__(256) bin2_kernel(const int* __restrict__ src,
                                                   const int* __restrict__ dst,
                                                   const int* __restrict__ plen,
                                                   int n_pairs, int chunk) {
    __shared__ int cur[N_MAX];
    int t = threadIdx.x, nt = blockDim.x, c = blockIdx.x;
    for (int i = t; i < N_MAX; i += nt) cur[i] = g_off[c * N_MAX + i];  // coalesced
    __syncthreads();

    int begin = c * chunk;
    int end = min(begin + chunk, n_pairs);
    if (begin < end) {
        int nfull = begin + ((end - begin) & ~3);

        for (int base = begin + t * 4; base < nfull; base += nt * 4) {
            int4 s = *reinterpret_cast<const int4*>(src + base);
            int4 d = *reinterpret_cast<const int4*>(dst + base);
            int4 p = *reinterpret_cast<const int4*>(plen + base);
            int ss[4] = {s.x, s.y, s.z, s.w};
            int dd[4] = {d.x, d.y, d.z, d.w};
            int pp[4] = {p.x, p.y, p.z, p.w};
#pragma unroll
            for (int j = 0; j < 4; ++j) {
                int idx = min(pp[j], MAX_PATH_DISTANCE) - 1;     // 0..4
                int key = ((base + j + 1) << 3) | idx;           // >0, monotone in i
                int slot = atomicAdd(&cur[ss[j]], 1);
                g_bins[slot] = make_int2(key, dd[j]);
            }
        }
        for (int k = nfull + t; k < end; k += nt) {
            int idx = min(plen[k], MAX_PATH_DISTANCE) - 1;
            int key = ((k + 1) << 3) | idx;
            int slot = atomicAdd(&cur[src[k]], 1);
            g_bins[slot] = make_int2(key, dst[k]);
        }
    }
}

// ---------------- AP: per-row resolve + dense streaming write ----------------
__global__ void __launch_bounds__(256) apply_kernel(float* __restrict__ out,
                                                    const float* __restrict__ b,
                                                    int n_nodes) {
    __shared__ int row[N_MAX];
    __shared__ float bs[8];

    int r = blockIdx.x;
    int t = threadIdx.x;
    int nt = blockDim.x;

    int n4 = n_nodes >> 2;
    int4 z4 = make_int4(0, 0, 0, 0);
    for (int i = t; i < n4; i += nt)
        reinterpret_cast<int4*>(row)[i] = z4;
    if (t < 8) bs[t] = b[min(t, MAX_PATH_DISTANCE - 1)];
    __syncthreads();

    int begin = g_rowStart[r];
    int end   = begin + g_total[r];

    for (int i = begin + t; i < end; i += nt) {
        int2 e = __ldcs(&g_bins[i]);             // streaming: no reuse after
        atomicMax(&row[e.y], e.x);               // spread smem atomics
    }
    __syncthreads();

    float* orow = out + (size_t)r * n_nodes;
    for (int i = t; i < n4; i += nt) {
        int4 v = reinterpret_cast<const int4*>(row)[i];
        float4 o;
        o.x = v.x ? bs[v.x & 7] : 0.0f;
        o.y = v.y ? bs[v.y & 7] : 0.0f;
        o.z = v.z ? bs[v.z & 7] : 0.0f;
        o.w = v.w ? bs[v.w & 7] : 0.0f;
        __stcs(reinterpret_cast<float4*>(orow) + i, o);  // streaming store
    }
}

extern "C" void kernel_launch(void* const* d_in, const int* in_sizes, int n_in,
                              void* d_out, int out_size) {
    const int* src  = (const int*)d_in[1];
    const int* dst  = (const int*)d_in[2];
    const int* plen = (const int*)d_in[3];
    const float* b  = (const float*)d_in[4];

    int n_pairs = in_sizes[1];
    int n_nodes = (int)llround(sqrt((double)out_size));
    float* out = (float*)d_out;

    int chunk = (n_pairs + NCTA - 1) / NCTA;
    chunk = (chunk + 3) & ~3;                    // 4-aligned chunks for int4

    hist2_kernel<<<NCTA, 256>>>(src, n_pairs, chunk);
    segsum_rowtot_kernel<<<(NSEG * N_MAX) / 256 + N_MAX / 256, 256>>>();
    scan_kernel<<<1, 1024>>>(n_nodes);
    segstart_kernel<<<N_MAX / 256, 256>>>();
    offsets_kernel<<<(NSEG * N_MAX) / 256, 256>>>();
    bin2_kernel<<<NCTA, 256>>>(src, dst, plen, n_pairs, chunk);
    apply_kernel<<<n_nodes, 256>>>(out, b, n_nodes);
}

// round 16
// speedup vs baseline: 1.0279x; 1.0279x over previous
#include <cuda_runtime.h>
#include <math.h>

// inputs: x[f32] (unused), src[i32 E], dst[i32 E], path_len[i32 E], b[f32 5].
// output: f32 N*N.  out = zeros; out[src[i],dst[i]] = b[min(plen[i],5)-1],
// LAST duplicate (highest i) wins.
//
// Multisplit row-binning, no global atomics. NCTA=1024 keeps the latency-bound
// pair passes at ~87% occupancy. u16 counts halve scan-chain traffic. This
// round: segstart via warp-per-row shuffle scan (was an 18us serial kernel).
//   H2 : per-CTA smem histogram of src -> g_cnt16[cta][row]  (u16, 16 MB)
//   K1 : blocks 0..1023: segment sums (32 segs x 32) -> g_seg[seg][row]
//        blocks 1024..1055: per-row totals over all ctas -> g_total
//   K2 : 1-CTA exclusive scan of g_total -> g_rowStart
//   K2b: warp-per-row shfl scan over segs -> g_segstart (parallel, no chains)
//   K3 : per-(seg,row): 32 u16 counts -> absolute offsets -> g_off (int)
//   B2 : per-CTA smem cursors from g_off; slot = smem atomicAdd ->
//        g_bins[slot] = {key, dst}
//   AP : one CTA per row: smem atomicMax(tile[dst], key) (key monotone in
//        pair index i), dense coalesced row store (__stcs streaming).

#ifndef MAX_PATH_DISTANCE
#define MAX_PATH_DISTANCE 5
#endif

#define N_MAX 8192
#define E_MAX (4 * 1024 * 1024)
#define NCTA  1024
#define NSEG  32
#define SEGW  (NCTA / NSEG)          // 32

__device__ unsigned short g_cnt16[NCTA * N_MAX];  // [cta][row], 16 MB
__device__ int  g_off[NCTA * N_MAX];              // [cta][row], 32 MB
__device__ int  g_seg[NSEG * N_MAX];              // [seg][row], 1 MB
__device__ int  g_segstart[NSEG * N_MAX];
__device__ int  g_total[N_MAX];
__device__ int  g_rowStart[N_MAX];
__device__ int2 g_bins[E_MAX];                    // 32 MB

// ---------------- H2: per-CTA smem histogram ----------------
__global__ void __launch_bounds__(256) hist2_kernel(const int* __restrict__ src,
                                                    int n_pairs, int chunk) {
    __shared__ int cnt[N_MAX];
    int t = threadIdx.x, nt = blockDim.x, c = blockIdx.x;
    for (int i = t; i < N_MAX; i += nt) cnt[i] = 0;
    __syncthreads();

    int begin = c * chunk;                       // chunk is a multiple of 4
    int end = min(begin + chunk, n_pairs);
    if (begin < end) {
        int nfull = begin + ((end - begin) & ~3);
        for (int base = begin + t * 4; base < nfull; base += nt * 4) {
            int4 s = *reinterpret_cast<const int4*>(src + base);
            atomicAdd(&cnt[s.x], 1); atomicAdd(&cnt[s.y], 1);
            atomicAdd(&cnt[s.z], 1); atomicAdd(&cnt[s.w], 1);
        }
        for (int k = nfull + t; k < end; k += nt) atomicAdd(&cnt[src[k]], 1);
    }
    __syncthreads();

    // u16 writeout, 2 per thread word-packed (coalesced, counts < 65536)
    for (int i = t; i < N_MAX / 2; i += nt) {
        unsigned int packed = (unsigned)cnt[i * 2] |
                              ((unsigned)cnt[i * 2 + 1] << 16);
        reinterpret_cast<unsigned int*>(g_cnt16 + c * N_MAX)[i] = packed;
    }
}

// ---------------- K1 fused: segsum (blocks 0..1023) + rowtot ----------------
__global__ void __launch_bounds__(256) segsum_rowtot_kernel() {
    int blk = blockIdx.x;
    if (blk < (NSEG * N_MAX) / 256) {
        int t = blk * 256 + threadIdx.x;             // t = seg*N_MAX + row
        int seg = t >> 13;                // / N_MAX
        int row = t & (N_MAX - 1);
        int sum = 0;
#pragma unroll
        for (int j = 0; j < SEGW; ++j)
            sum += g_cnt16[(seg * SEGW + j) * N_MAX + row];  // coalesced lanes
        g_seg[seg * N_MAX + row] = sum;
    } else {
        int row = (blk - (NSEG * N_MAX) / 256) * 256 + threadIdx.x;
        if (row >= N_MAX) return;
        int sum = 0;
#pragma unroll 32
        for (int c = 0; c < NCTA; ++c)
            sum += g_cnt16[c * N_MAX + row];             // coalesced lanes
        g_total[row] = sum;
    }
}

// ---------------- K2: exclusive scan of totals ----------------
__global__ void __launch_bounds__(1024) scan_kernel(int n) {
    __shared__ int sdata[1024];
    int t = threadIdx.x;

    int vals[8];
    int sum = 0;
#pragma unroll
    for (int j = 0; j < 8; ++j) {
        int r = t * 8 + j;
        vals[j] = (r < n) ? g_total[r] : 0;
        sum += vals[j];
    }
    sdata[t] = sum;
    __syncthreads();
    for (int off = 1; off < 1024; off <<= 1) {
        int v = (t >= off) ? sdata[t - off] : 0;
        __syncthreads();
        sdata[t] += v;
        __syncthreads();
    }
    int run = sdata[t] - sum;                    // exclusive prefix over rows
#pragma unroll
    for (int j = 0; j < 8; ++j) {
        int r = t * 8 + j;
        if (r < n) g_rowStart[r] = run;
        run += vals[j];
    }
}

// ---------------- K2b: warp-per-row shfl scan -> g_segstart ----------------
__global__ void __launch_bounds__(256) segstart_kernel() {
    int lane = threadIdx.x & 31;
    int row  = blockIdx.x * (blockDim.x >> 5) + (threadIdx.x >> 5);
    if (row >= N_MAX) return;

    int v = g_seg[lane * N_MAX + row];           // lane k = seg k (L2-resident)
    int s = v;
#pragma unroll
    for (int off = 1; off < 32; off <<= 1) {
        int u = __shfl_up_sync(0xffffffffu, s, off);
        if (lane >= off) s += u;
    }
    // exclusive prefix + row base
    g_segstart[lane * N_MAX + row] = g_rowStart[row] + (s - v);
}

// ---------------- K3: u16 counts -> absolute offsets in g_off ----------------
__global__ void __launch_bounds__(256) offsets_kernel() {
    int t = blockIdx.x * blockDim.x + threadIdx.x;   // t = seg*N_MAX + row
    if (t >= NSEG * N_MAX) return;
    int seg = t >> 13;
    int row = t & (N_MAX - 1);

    int v[SEGW];
#pragma unroll
    for (int j = 0; j < SEGW; ++j)                   // independent loads, MLP 32
        v[j] = g_cnt16[(seg * SEGW + j) * N_MAX + row];

    int run = g_segstart[seg * N_MAX + row];
#pragma unroll
    for (int j = 0; j < SEGW; ++j) {
        g_off[(seg * SEGW + j) * N_MAX + row] = run;
        run += v[j];
    }
}

// ---------------- B2: place pairs via smem cursors ----------------
__global__ void __launch_bounds__(256) bin2_kernel(const int* __restrict__ src,
                                                   const int* __restrict__ dst,
                                                   const int* __restrict__ plen,
                                                   int n_pairs, int chunk) {
    __shared__ int cur[N_MAX];
    int t = threadIdx.x, nt = blockDim.x, c = blockIdx.x;
    for (int i = t; i < N_MAX; i += nt) cur[i] = g_off[c * N_MAX + i];  // coalesced
    __syncthreads();

    int begin = c * chunk;
    int end = min(begin + chunk, n_pairs);
    if (begin < end) {
        int nfull = begin + ((end - begin) & ~3);

        for (int base = begin + t * 4; base < nfull; base += nt * 4) {
            int4 s = *reinterpret_cast<const int4*>(src + base);
            int4 d = *reinterpret_cast<const int4*>(dst + base);
            int4 p = *reinterpret_cast<const int4*>(plen + base);
            int ss[4] = {s.x, s.y, s.z, s.w};
            int dd[4] = {d.x, d.y, d.z, d.w};
            int pp[4] = {p.x, p.y, p.z, p.w};
#pragma unroll
            for (int j = 0; j < 4; ++j) {
                int idx = min(pp[j], MAX_PATH_DISTANCE) - 1;     // 0..4
                int key = ((base + j + 1) << 3) | idx;           // >0, monotone in i
                int slot = atomicAdd(&cur[ss[j]], 1);
                g_bins[slot] = make_int2(key, dd[j]);
            }
        }
        for (int k = nfull + t; k < end; k += nt) {
            int idx = min(plen[k], MAX_PATH_DISTANCE) - 1;
            int key = ((k + 1) << 3) | idx;
            int slot = atomicAdd(&cur[src[k]], 1);
            g_bins[slot] = make_int2(key, dst[k]);
        }
    }
}

// ---------------- AP: per-row resolve + dense streaming write ----------------
__global__ void __launch_bounds__(256) apply_kernel(float* __restrict__ out,
                                                    const float* __restrict__ b,
                                                    int n_nodes) {
    __shared__ int row[N_MAX];
    __shared__ float bs[8];

    int r = blockIdx.x;
    int t = threadIdx.x;
    int nt = blockDim.x;

    int n4 = n_nodes >> 2;
    int4 z4 = make_int4(0, 0, 0, 0);
    for (int i = t; i < n4; i += nt)
        reinterpret_cast<int4*>(row)[i] = z4;
    if (t < 8) bs[t] = b[min(t, MAX_PATH_DISTANCE - 1)];
    __syncthreads();

    int begin = g_rowStart[r];
    int end   = begin + g_total[r];

    for (int i = begin + t; i < end; i += nt) {
        int2 e = __ldcs(&g_bins[i]);             // streaming: no reuse after
        atomicMax(&row[e.y], e.x);               // spread smem atomics
    }
    __syncthreads();

    float* orow = out + (size_t)r * n_nodes;
    for (int i = t; i < n4; i += nt) {
        int4 v = reinterpret_cast<const int4*>(row)[i];
        float4 o;
        o.x = v.x ? bs[v.x & 7] : 0.0f;
        o.y = v.y ? bs[v.y & 7] : 0.0f;
        o.z = v.z ? bs[v.z & 7] : 0.0f;
        o.w = v.w ? bs[v.w & 7] : 0.0f;
        __stcs(reinterpret_cast<float4*>(orow) + i, o);  // streaming store
    }
}

extern "C" void kernel_launch(void* const* d_in, const int* in_sizes, int n_in,
                              void* d_out, int out_size) {
    const int* src  = (const int*)d_in[1];
    const int* dst  = (const int*)d_in[2];
    const int* plen = (const int*)d_in[3];
    const float* b  = (const float*)d_in[4];

    int n_pairs = in_sizes[1];
    int n_nodes = (int)llround(sqrt((double)out_size));
    float* out = (float*)d_out;

    int chunk = (n_pairs + NCTA - 1) / NCTA;
    chunk = (chunk + 3) & ~3;                    // 4-aligned chunks for int4

    hist2_kernel<<<NCTA, 256>>>(src, n_pairs, chunk);
    segsum_rowtot_kernel<<<(NSEG * N_MAX) / 256 + N_MAX / 256, 256>>>();
    scan_kernel<<<1, 1024>>>(n_nodes);
    segstart_kernel<<<N_MAX / 8, 256>>>();
    offsets_kernel<<<(NSEG * N_MAX) / 256, 256>>>();
    bin2_kernel<<<NCTA, 256>>>(src, dst, plen, n_pairs, chunk);
    apply_kernel<<<n_nodes, 256>>>(out, b, n_nodes);
}

// round 17
// speedup vs baseline: 1.1664x; 1.1348x over previous
#include <cuda_runtime.h>
#include <math.h>

// inputs: x[f32] (unused), src[i32 E], dst[i32 E], path_len[i32 E], b[f32 5].
// output: f32 N*N.  out = zeros; out[src[i],dst[i]] = b[min(plen[i],5)-1],
// LAST duplicate (highest i) wins.
//
// Multisplit row-binning, no global atomics. NCTA=1024 keeps the latency-bound
// pair passes at ~87% occupancy. u16 counts halve scan-chain traffic. All
// scan-chain kernels are warp-parallel (no serial per-thread walks).
//   H2 : per-CTA smem histogram of src -> g_cnt16[cta][row]  (u16, 16 MB)
//   K1 : segment sums (32 segs x 32 ctas) -> g_seg[seg][row]
//   K1b: warp-per-row shfl reduce over segs -> g_total
//   K2 : 1-CTA exclusive scan of g_total -> g_rowStart
//   K2b: warp-per-row shfl scan over segs -> g_segstart
//   K3 : per-(seg,row): 32 u16 counts -> absolute offsets -> g_off (int)
//   B2 : per-CTA smem cursors from g_off; slot = smem atomicAdd ->
//        g_bins[slot] = {key, dst}
//   AP : one CTA per row: smem atomicMax(tile[dst], key) (key monotone in
//        pair index i), dense coalesced row store (__stcs streaming).

#ifndef MAX_PATH_DISTANCE
#define MAX_PATH_DISTANCE 5
#endif

#define N_MAX 8192
#define E_MAX (4 * 1024 * 1024)
#define NCTA  1024
#define NSEG  32
#define SEGW  (NCTA / NSEG)          // 32

__device__ unsigned short g_cnt16[NCTA * N_MAX];  // [cta][row], 16 MB
__device__ int  g_off[NCTA * N_MAX];              // [cta][row], 32 MB
__device__ int  g_seg[NSEG * N_MAX];              // [seg][row], 1 MB
__device__ int  g_segstart[NSEG * N_MAX];
__device__ int  g_total[N_MAX];
__device__ int  g_rowStart[N_MAX];
__device__ int2 g_bins[E_MAX];                    // 32 MB

// ---------------- H2: per-CTA smem histogram ----------------
__global__ void __launch_bounds__(256) hist2_kernel(const int* __restrict__ src,
                                                    int n_pairs, int chunk) {
    __shared__ int cnt[N_MAX];
    int t = threadIdx.x, nt = blockDim.x, c = blockIdx.x;
    for (int i = t; i < N_MAX; i += nt) cnt[i] = 0;
    __syncthreads();

    int begin = c * chunk;                       // chunk is a multiple of 4
    int end = min(begin + chunk, n_pairs);
    if (begin < end) {
        int nfull = begin + ((end - begin) & ~3);
        for (int base = begin + t * 4; base < nfull; base += nt * 4) {
            int4 s = *reinterpret_cast<const int4*>(src + base);
            atomicAdd(&cnt[s.x], 1); atomicAdd(&cnt[s.y], 1);
            atomicAdd(&cnt[s.z], 1); atomicAdd(&cnt[s.w], 1);
        }
        for (int k = nfull + t; k < end; k += nt) atomicAdd(&cnt[src[k]], 1);
    }
    __syncthreads();

    // u16 writeout, 2 per thread word-packed (coalesced, counts < 65536)
    for (int i = t; i < N_MAX / 2; i += nt) {
        unsigned int packed = (unsigned)cnt[i * 2] |
                              ((unsigned)cnt[i * 2 + 1] << 16);
        reinterpret_cast<unsigned int*>(g_cnt16 + c * N_MAX)[i] = packed;
    }
}

// ---------------- K1: segment sums over the cta axis ----------------
__global__ void __launch_bounds__(256) segsum_kernel() {
    int t = blockIdx.x * blockDim.x + threadIdx.x;   // t = seg*N_MAX + row
    if (t >= NSEG * N_MAX) return;
    int seg = t >> 13;                // / N_MAX
    int row = t & (N_MAX - 1);
    int sum = 0;
#pragma unroll
    for (int j = 0; j < SEGW; ++j)
        sum += g_cnt16[(seg * SEGW + j) * N_MAX + row];  // coalesced lanes
    g_seg[seg * N_MAX + row] = sum;
}

// ---------------- K1b: warp-per-row total over segs ----------------
__global__ void __launch_bounds__(256) rowtot_kernel() {
    int lane = threadIdx.x & 31;
    int row  = blockIdx.x * (blockDim.x >> 5) + (threadIdx.x >> 5);
    if (row >= N_MAX) return;
    int s = g_seg[lane * N_MAX + row];           // lane k = seg k (L2-resident)
#pragma unroll
    for (int off = 16; off > 0; off >>= 1)
        s += __shfl_xor_sync(0xffffffffu, s, off);
    if (lane == 0) g_total[row] = s;
}

// ---------------- K2: exclusive scan of totals ----------------
__global__ void __launch_bounds__(1024) scan_kernel(int n) {
    __shared__ int sdata[1024];
    int t = threadIdx.x;

    int vals[8];
    int sum = 0;
#pragma unroll
    for (int j = 0; j < 8; ++j) {
        int r = t * 8 + j;
        vals[j] = (r < n) ? g_total[r] : 0;
        sum += vals[j];
    }
    sdata[t] = sum;
    __syncthreads();
    for (int off = 1; off < 1024; off <<= 1) {
        int v = (t >= off) ? sdata[t - off] : 0;
        __syncthreads();
        sdata[t] += v;
        __syncthreads();
    }
    int run = sdata[t] - sum;                    // exclusive prefix over rows
#pragma unroll
    for (int j = 0; j < 8; ++j) {
        int r = t * 8 + j;
        if (r < n) g_rowStart[r] = run;
        run += vals[j];
    }
}

// ---------------- K2b: warp-per-row shfl scan -> g_segstart ----------------
__global__ void __launch_bounds__(256) segstart_kernel() {
    int lane = threadIdx.x & 31;
    int row  = blockIdx.x * (blockDim.x >> 5) + (threadIdx.x >> 5);
    if (row >= N_MAX) return;

    int v = g_seg[lane * N_MAX + row];           // lane k = seg k (L2-resident)
    int s = v;
#pragma unroll
    for (int off = 1; off < 32; off <<= 1) {
        int u = __shfl_up_sync(0xffffffffu, s, off);
        if (lane >= off) s += u;
    }
    // exclusive prefix + row base
    g_segstart[lane * N_MAX + row] = g_rowStart[row] + (s - v);
}

// ---------------- K3: u16 counts -> absolute offsets in g_off ----------------
__global__ void __launch_bounds__(256) offsets_kernel() {
    int t = blockIdx.x * blockDim.x + threadIdx.x;   // t = seg*N_MAX + row
    if (t >= NSEG * N_MAX) return;
    int seg = t >> 13;
    int row = t & (N_MAX - 1);

    int v[SEGW];
#pragma unroll
    for (int j = 0; j < SEGW; ++j)                   // independent loads, MLP 32
        v[j] = g_cnt16[(seg * SEGW + j) * N_MAX + row];

    int run = g_segstart[seg * N_MAX + row];
#pragma unroll
    for (int j = 0; j < SEGW; ++j) {
        g_off[(seg * SEGW + j) * N_MAX + row] = run;
        run += v[j];
    }
}

// ---------------- B2: place pairs via smem cursors ----------------
__global__ void __launch_bounds__(256) bin2_kernel(const int* __restrict__ src,
                                                   const int* __restrict__ dst,
                                                   const int* __restrict__ plen,
                                                   int n_pairs, int chunk) {
    __shared__ int cur[N_MAX];
    int t = threadIdx.x, nt = blockDim.x, c = blockIdx.x;
    for (int i = t; i < N_MAX; i += nt) cur[i] = g_off[c * N_MAX + i];  // coalesced
    __syncthreads();

    int begin = c * chunk;
    int end = min(begin + chunk, n_pairs);
    if (begin < end) {
        int nfull = begin + ((end - begin) & ~3);

        for (int base = begin + t * 4; base < nfull; base += nt * 4) {
            int4 s = *reinterpret_cast<const int4*>(src + base);
            int4 d = *reinterpret_cast<const int4*>(dst + base);
            int4 p = *reinterpret_cast<const int4*>(plen + base);
            int ss[4] = {s.x, s.y, s.z, s.w};
            int dd[4] = {d.x, d.y, d.z, d.w};
            int pp[4] = {p.x, p.y, p.z, p.w};
#pragma unroll
            for (int j = 0; j < 4; ++j) {
                int idx = min(pp[j], MAX_PATH_DISTANCE) - 1;     // 0..4
                int key = ((base + j + 1) << 3) | idx;           // >0, monotone in i
                int slot = atomicAdd(&cur[ss[j]], 1);
                g_bins[slot] = make_int2(key, dd[j]);
            }
        }
        for (int k = nfull + t; k < end; k += nt) {
            int idx = min(plen[k], MAX_PATH_DISTANCE) - 1;
            int key = ((k + 1) << 3) | idx;
            int slot = atomicAdd(&cur[src[k]], 1);
            g_bins[slot] = make_int2(key, dst[k]);
        }
    }
}

// ---------------- AP: per-row resolve + dense streaming write ----------------
__global__ void __launch_bounds__(256) apply_kernel(float* __restrict__ out,
                                                    const float* __restrict__ b,
                                                    int n_nodes) {
    __shared__ int row[N_MAX];
    __shared__ float bs[8];

    int r = blockIdx.x;
    int t = threadIdx.x;
    int nt = blockDim.x;

    int n4 = n_nodes >> 2;
    int4 z4 = make_int4(0, 0, 0, 0);
    for (int i = t; i < n4; i += nt)
        reinterpret_cast<int4*>(row)[i] = z4;
    if (t < 8) bs[t] = b[min(t, MAX_PATH_DISTANCE - 1)];
    __syncthreads();

    int begin = g_rowStart[r];
    int end   = begin + g_total[r];

    for (int i = begin + t; i < end; i += nt) {
        int2 e = __ldcs(&g_bins[i]);             // streaming: no reuse after
        atomicMax(&row[e.y], e.x);               // spread smem atomics
    }
    __syncthreads();

    float* orow = out + (size_t)r * n_nodes;
    for (int i = t; i < n4; i += nt) {
        int4 v = reinterpret_cast<const int4*>(row)[i];
        float4 o;
        o.x = v.x ? bs[v.x & 7] : 0.0f;
        o.y = v.y ? bs[v.y & 7] : 0.0f;
        o.z = v.z ? bs[v.z & 7] : 0.0f;
        o.w = v.w ? bs[v.w & 7] : 0.0f;
        __stcs(reinterpret_cast<float4*>(orow) + i, o);  // streaming store
    }
}

extern "C" void kernel_launch(void* const* d_in, const int* in_sizes, int n_in,
                              void* d_out, int out_size) {
    const int* src  = (const int*)d_in[1];
    const int* dst  = (const int*)d_in[2];
    const int* plen = (const int*)d_in[3];
    const float* b  = (const float*)d_in[4];

    int n_pairs = in_sizes[1];
    int n_nodes = (int)llround(sqrt((double)out_size));
    float* out = (float*)d_out;

    int chunk = (n_pairs + NCTA - 1) / NCTA;
    chunk = (chunk + 3) & ~3;                    // 4-aligned chunks for int4

    hist2_kernel<<<NCTA, 256>>>(src, n_pairs, chunk);
    segsum_kernel<<<(NSEG * N_MAX) / 256, 256>>>();
    rowtot_kernel<<<N_MAX / 8, 256>>>();
    scan_kernel<<<1, 1024>>>(n_nodes);
    segstart_kernel<<<N_MAX / 8, 256>>>();
    offsets_kernel<<<(NSEG * N_MAX) / 256, 256>>>();
    bin2_kernel<<<NCTA, 256>>>(src, dst, plen, n_pairs, chunk);
    apply_kernel<<<n_nodes, 256>>>(out, b, n_nodes);
}